// round 1
// baseline (speedup 1.0000x reference)
#include <cuda_runtime.h>
#include <math.h>

// ---------------- problem constants ----------------
#define E_TOT 480000
#define N_TOT 30000
#define EMB   128
#define OUTD  256
#define NR    6
#define NA    95

// scratch for scatter-sum (node branch): [N_TOT][EMB] fp32, 15.36 MB (L2-resident)
__device__ float g_agg[(size_t)N_TOT * EMB];

// ---------------- fused-MLP block config ----------------
constexpr int ME = 64;            // rows per block
constexpr int SH = 257;           // smem row stride for activations (bank-conflict-free)
constexpr int SW = 33;            // smem row stride for weight tile
constexpr int NTHREADS = 256;     // 16x16 thread tile
constexpr int SMEM_FLOATS = 2 * ME * SH + 256 * SW;   // H0, H1, Ws
constexpr int SMEM_BYTES  = SMEM_FLOATS * 4;          // 165376 B

// Block-level GEMM: B[64][O] = act(A[64][K] @ W[O][K]^T + bias)
// A, B in shared memory (stride SH). W streamed from global in [O][32] tiles.
// Thread (tx,ty): rows e = ty+16i (i<4), cols o = tx+16j (j<NJ).
template<int K, int O, bool SILU, bool TO_GLOBAL>
__device__ __forceinline__ void mm_block(
    const float* __restrict__ W, const float* __restrict__ bias,
    const float* As, float* Bs, float* Ws,
    float* gout, int row0, int nrows,
    int tid, int tx, int ty)
{
    constexpr int NJ = (O + 15) / 16;
    float acc[4][NJ];
#pragma unroll
    for (int i = 0; i < 4; i++)
#pragma unroll
        for (int j = 0; j < NJ; j++) acc[i][j] = 0.f;

    for (int k0 = 0; k0 < K; k0 += 32) {
        __syncthreads();   // prev readers of Ws done / prev stage writes visible
        // load W tile [O][32] (float4, coalesced within a row)
        for (int idx = tid; idx < O * 8; idx += NTHREADS) {
            int o = idx >> 3, kq = idx & 7;
            float4 v = *reinterpret_cast<const float4*>(W + (size_t)o * K + k0 + kq * 4);
            float* d = Ws + o * SW + kq * 4;
            d[0] = v.x; d[1] = v.y; d[2] = v.z; d[3] = v.w;
        }
        __syncthreads();
#pragma unroll
        for (int kk = 0; kk < 32; kk++) {
            float a[4];
#pragma unroll
            for (int i = 0; i < 4; i++) a[i] = As[(ty + 16 * i) * SH + k0 + kk];
#pragma unroll
            for (int j = 0; j < NJ; j++) {
                float w = Ws[(tx + 16 * j) * SW + kk];   // garbage if o>=O, never stored
#pragma unroll
                for (int i = 0; i < 4; i++) acc[i][j] = fmaf(a[i], w, acc[i][j]);
            }
        }
    }
    // epilogue
#pragma unroll
    for (int j = 0; j < NJ; j++) {
        int o = tx + 16 * j;
        if (o < O) {
            float b = bias ? __ldg(bias + o) : 0.f;
#pragma unroll
            for (int i = 0; i < 4; i++) {
                int e = ty + 16 * i;
                float v = acc[i][j] + b;
                if (SILU) v = v / (1.f + __expf(-v));
                if (TO_GLOBAL) {
                    if (row0 + e < nrows) gout[(size_t)(row0 + e) * O + o] = v;
                } else {
                    Bs[e * SH + o] = v;
                }
            }
        }
    }
    __syncthreads();
}

// In-place LayerNorm over 256 cols of H[64][SH]. 8 warps, 8 rows each.
__device__ __forceinline__ void layernorm_block(
    float* H, const float* __restrict__ g, const float* __restrict__ b, int tid)
{
    int warp = tid >> 5, lane = tid & 31;
    for (int rr = 0; rr < 8; rr++) {
        int r = warp * 8 + rr;
        float s = 0.f, s2 = 0.f;
#pragma unroll
        for (int t = 0; t < 8; t++) {
            float x = H[r * SH + lane + 32 * t];
            s += x; s2 += x * x;
        }
#pragma unroll
        for (int off = 16; off; off >>= 1) {
            s  += __shfl_xor_sync(0xffffffffu, s,  off);
            s2 += __shfl_xor_sync(0xffffffffu, s2, off);
        }
        float mu  = s * (1.f / 256.f);
        float var = s2 * (1.f / 256.f) - mu * mu;
        float rs  = rsqrtf(var + 1e-5f);
#pragma unroll
        for (int t = 0; t < 8; t++) {
            int k = lane + 32 * t;
            float x = H[r * SH + k];
            H[r * SH + k] = __ldg(g + k) * (x - mu) * rs + __ldg(b + k);
        }
    }
    __syncthreads();
}

// ---------------- edge branch: fully fused ----------------
__global__ void __launch_bounds__(NTHREADS) edge_kernel(
    const float* __restrict__ m, const float* __restrict__ rbf,
    const float* __restrict__ Wr, const float* __restrict__ Wup,
    const float* __restrict__ lng, const float* __restrict__ lnb,
    const float* __restrict__ Wd, const float* __restrict__ bd,
    const float* __restrict__ Wf, float* __restrict__ out)
{
    extern __shared__ float smem[];
    float* H0 = smem;
    float* H1 = H0 + ME * SH;
    float* Ws = H1 + ME * SH;
    int tid = threadIdx.x;
    int tx = tid & 15, ty = tid >> 4;
    int row0 = blockIdx.x * ME;

    // stage0: tmp = m * (rbf @ Wr^T), into H0[:, :128]
    float* Wrs = Ws;            // [128][6]
    float* Rbs = Ws + EMB * NR; // [64][6]
    for (int idx = tid; idx < EMB * NR; idx += NTHREADS) Wrs[idx] = Wr[idx];
    for (int idx = tid; idx < ME * NR;  idx += NTHREADS) Rbs[idx] = rbf[(size_t)row0 * NR + idx];
    __syncthreads();
    for (int idx = tid; idx < ME * EMB; idx += NTHREADS) {
        int e = idx >> 7, k = idx & 127;
        const float* rb = Rbs + e * NR;
        const float* wr = Wrs + k * NR;
        float c = rb[0]*wr[0] + rb[1]*wr[1] + rb[2]*wr[2]
                + rb[3]*wr[3] + rb[4]*wr[4] + rb[5]*wr[5];
        H0[e * SH + k] = m[(size_t)(row0 + e) * EMB + k] * c;
    }
    __syncthreads();

    mm_block<EMB,  OUTD, false, false>(Wup, nullptr, H0, H1, Ws, nullptr, 0, 0, tid, tx, ty);
    layernorm_block(H1, lng, lnb, tid);
    mm_block<OUTD, OUTD, true,  false>(Wd + 0 * OUTD * OUTD, bd + 0 * OUTD, H1, H0, Ws, nullptr, 0, 0, tid, tx, ty);
    mm_block<OUTD, OUTD, true,  false>(Wd + 1 * OUTD * OUTD, bd + 1 * OUTD, H0, H1, Ws, nullptr, 0, 0, tid, tx, ty);
    mm_block<OUTD, OUTD, true,  false>(Wd + 2 * OUTD * OUTD, bd + 2 * OUTD, H1, H0, Ws, nullptr, 0, 0, tid, tx, ty);
    mm_block<OUTD, 2,    false, true >(Wf, nullptr, H0, nullptr, Ws, out, row0, E_TOT, tid, tx, ty);
}

// ---------------- node branch ----------------
__global__ void zero_agg_kernel()
{
    size_t n = (size_t)N_TOT * EMB;
    for (size_t i = (size_t)blockIdx.x * blockDim.x + threadIdx.x; i < n;
         i += (size_t)gridDim.x * blockDim.x)
        g_agg[i] = 0.f;
}

__global__ void __launch_bounds__(NTHREADS) scatter_kernel(
    const float* __restrict__ m, const float* __restrict__ rbf,
    const int* __restrict__ src, const float* __restrict__ Wr)
{
    __shared__ float Wrs[EMB * NR];
    for (int idx = threadIdx.x; idx < EMB * NR; idx += NTHREADS) Wrs[idx] = Wr[idx];
    __syncthreads();
    int sub = threadIdx.x >> 7;     // 2 edges per block-iteration
    int k   = threadIdx.x & 127;
    for (long long e = (long long)blockIdx.x * 2 + sub; e < E_TOT;
         e += (long long)gridDim.x * 2) {
        const float* rb = rbf + e * NR;
        float r0 = __ldg(rb+0), r1 = __ldg(rb+1), r2 = __ldg(rb+2);
        float r3 = __ldg(rb+3), r4 = __ldg(rb+4), r5 = __ldg(rb+5);
        const float* wr = Wrs + k * NR;
        float c = r0*wr[0] + r1*wr[1] + r2*wr[2] + r3*wr[3] + r4*wr[4] + r5*wr[5];
        float v = m[(size_t)e * EMB + k] * c;
        int s = __ldg(src + e);
        atomicAdd(g_agg + (size_t)s * EMB + k, v);
    }
}

__global__ void __launch_bounds__(NTHREADS) node_kernel(
    const float* __restrict__ Wup,
    const float* __restrict__ lng, const float* __restrict__ lnb,
    const float* __restrict__ Wd, const float* __restrict__ bd,
    const float* __restrict__ Wf, float* __restrict__ out)
{
    extern __shared__ float smem[];
    float* H0 = smem;
    float* H1 = H0 + ME * SH;
    float* Ws = H1 + ME * SH;
    int tid = threadIdx.x;
    int tx = tid & 15, ty = tid >> 4;
    int row0 = blockIdx.x * ME;

    // stage0: load agg rows (zero-pad tail)
    for (int idx = tid; idx < ME * EMB; idx += NTHREADS) {
        int e = idx >> 7, k = idx & 127;
        int r = row0 + e;
        H0[e * SH + k] = (r < N_TOT) ? g_agg[(size_t)r * EMB + k] : 0.f;
    }
    __syncthreads();

    mm_block<EMB,  OUTD, false, false>(Wup, nullptr, H0, H1, Ws, nullptr, 0, 0, tid, tx, ty);
    layernorm_block(H1, lng, lnb, tid);
    mm_block<OUTD, OUTD, true,  false>(Wd + 0 * OUTD * OUTD, bd + 0 * OUTD, H1, H0, Ws, nullptr, 0, 0, tid, tx, ty);
    mm_block<OUTD, OUTD, true,  false>(Wd + 1 * OUTD * OUTD, bd + 1 * OUTD, H0, H1, Ws, nullptr, 0, 0, tid, tx, ty);
    mm_block<OUTD, OUTD, true,  false>(Wd + 2 * OUTD * OUTD, bd + 2 * OUTD, H1, H0, Ws, nullptr, 0, 0, tid, tx, ty);
    mm_block<OUTD, NA,   false, true >(Wf, nullptr, H0, nullptr, Ws, out, row0, N_TOT, tid, tx, ty);
}

// ---------------- launch ----------------
extern "C" void kernel_launch(void* const* d_in, const int* in_sizes, int n_in,
                              void* d_out, int out_size)
{
    const float* m       = (const float*)d_in[0];
    const float* rbf     = (const float*)d_in[1];
    const int*   src     = (const int*)  d_in[2];
    const float* W_rbf_e = (const float*)d_in[3];
    const float* W_up_e  = (const float*)d_in[4];
    const float* ln_g_e  = (const float*)d_in[5];
    const float* ln_b_e  = (const float*)d_in[6];
    const float* Wd_e    = (const float*)d_in[7];
    const float* bd_e    = (const float*)d_in[8];
    const float* W_fin_e = (const float*)d_in[9];
    const float* W_rbf_n = (const float*)d_in[10];
    const float* W_up_n  = (const float*)d_in[11];
    const float* ln_g_n  = (const float*)d_in[12];
    const float* ln_b_n  = (const float*)d_in[13];
    const float* Wd_n    = (const float*)d_in[14];
    const float* bd_n    = (const float*)d_in[15];
    const float* W_fin_n = (const float*)d_in[16];

    float* edge_out = (float*)d_out;                       // [E,2]
    float* node_out = (float*)d_out + (size_t)E_TOT * 2;   // [N,95]

    cudaFuncSetAttribute(edge_kernel, cudaFuncAttributeMaxDynamicSharedMemorySize, SMEM_BYTES);
    cudaFuncSetAttribute(node_kernel, cudaFuncAttributeMaxDynamicSharedMemorySize, SMEM_BYTES);

    zero_agg_kernel<<<512, 256>>>();
    scatter_kernel<<<1184, 256>>>(m, rbf, src, W_rbf_n);
    edge_kernel<<<E_TOT / ME, NTHREADS, SMEM_BYTES>>>(
        m, rbf, W_rbf_e, W_up_e, ln_g_e, ln_b_e, Wd_e, bd_e, W_fin_e, edge_out);
    node_kernel<<<(N_TOT + ME - 1) / ME, NTHREADS, SMEM_BYTES>>>(
        W_up_n, ln_g_n, ln_b_n, Wd_n, bd_n, W_fin_n, node_out);
}

// round 3
// speedup vs baseline: 3.5766x; 3.5766x over previous
#include <cuda_runtime.h>
#include <math.h>
#include <stdint.h>

#define E_TOT 480000
#define N_TOT 30000

constexpr int SA  = 260;   // A smem row stride (floats), 260 % 32 == 4 -> conflict-free frags
constexpr int SWK = 36;    // W tile row stride (floats), 36 % 32 == 4

// smem layout (floats)
#define F_A   0        // 128 x 260            = 33280
#define F_WB  33280    // 2 x 256 x 36         = 18432
#define F_S4  51712    // 128 x 4 (LN partials)=   512
#define F_WR  52224    // 128 x 6 (edge stage0)=   768
#define SMEM_FLOATS 52992
#define SMEM_BYTES  (SMEM_FLOATS * 4)

// scatter-sum scratch [N][128] fp32 (15.4 MB)
__device__ float g_agg[(size_t)N_TOT * 128];
// rna-tf32 converted weights
#define OFF_UP_E 0
#define OFF_WD_E 32768
#define OFF_WF_E 229376
#define OFF_UP_N 229888
#define OFF_WD_N 262656
#define OFF_WF_N 459264
#define WCVT_TOT 483584
__device__ __align__(16) float g_wcvt[WCVT_TOT];

// ---------------- helpers ----------------
__device__ __forceinline__ uint32_t smem_u32(const void* p) {
    uint32_t a;
    asm("{ .reg .u64 t; cvta.to.shared.u64 t, %1; cvt.u32.u64 %0, t; }" : "=r"(a) : "l"(p));
    return a;
}
__device__ __forceinline__ float cvt_rna(float x) {
    uint32_t u;
    asm("cvt.rna.tf32.f32 %0, %1;" : "=r"(u) : "f"(x));
    return __uint_as_float(u);
}
__device__ __forceinline__ void mma8(float* c, const uint32_t a[4], const uint32_t b[2]) {
    asm volatile("mma.sync.aligned.m16n8k8.row.col.f32.tf32.tf32.f32 "
        "{%0,%1,%2,%3},{%4,%5,%6,%7},{%8,%9},{%0,%1,%2,%3};"
        : "+f"(c[0]), "+f"(c[1]), "+f"(c[2]), "+f"(c[3])
        : "r"(a[0]), "r"(a[1]), "r"(a[2]), "r"(a[3]), "r"(b[0]), "r"(b[1]));
}
__device__ __forceinline__ void cpa16(uint32_t s, const float* g) {
    asm volatile("cp.async.cg.shared.global [%0], [%1], 16;" :: "r"(s), "l"(g));
}

// GEMM: C[128, 8*NTW*2] += A[128,K] @ W[rows,K]^T  (W tf32, streamed; A tf32 in smem)
// warps: wm = wid&3 (rows 32*wm), wn = wid>>2 (cols wn*NTW*8)
template<int K, int WR, int NTW>
__device__ __forceinline__ void gemm_layer(
    const float* __restrict__ Wg, int wrows,
    const float* __restrict__ A, float* __restrict__ Wb, float* c,
    int tid, int wm, int wn, int g, int t)
{
    constexpr int NT = K / 32;
    // prefetch tile 0
    for (int idx = tid; idx < WR * 8; idx += 256) {
        int n = idx >> 3, q = idx & 7;
        if (n < wrows) cpa16(smem_u32(Wb + n * SWK + q * 4), Wg + (size_t)n * K + q * 4);
    }
    asm volatile("cp.async.commit_group;");

    for (int kt = 0; kt < NT; kt++) {
        const float* cur = Wb + (kt & 1) * (WR * SWK);
        if (kt + 1 < NT) {
            float* nxt = Wb + ((kt + 1) & 1) * (WR * SWK);
            for (int idx = tid; idx < WR * 8; idx += 256) {
                int n = idx >> 3, q = idx & 7;
                if (n < wrows)
                    cpa16(smem_u32(nxt + n * SWK + q * 4),
                          Wg + (size_t)n * K + (kt + 1) * 32 + q * 4);
            }
            asm volatile("cp.async.commit_group;");
            asm volatile("cp.async.wait_group 1;");
        } else {
            asm volatile("cp.async.wait_group 0;");
        }
        __syncthreads();
#pragma unroll
        for (int ks = 0; ks < 4; ks++) {
            int k0 = ks * 8;
            uint32_t a[2][4];
#pragma unroll
            for (int mt = 0; mt < 2; mt++) {
                const float* Ab = A + (32 * wm + 16 * mt) * SA + kt * 32 + k0;
                a[mt][0] = __float_as_uint(Ab[g * SA + t]);
                a[mt][1] = __float_as_uint(Ab[(g + 8) * SA + t]);
                a[mt][2] = __float_as_uint(Ab[g * SA + t + 4]);
                a[mt][3] = __float_as_uint(Ab[(g + 8) * SA + t + 4]);
            }
#pragma unroll
            for (int nt = 0; nt < NTW; nt++) {
                int n0 = wn * (NTW * 8) + nt * 8;
                uint32_t b[2];
                b[0] = __float_as_uint(cur[(n0 + g) * SWK + k0 + t]);
                b[1] = __float_as_uint(cur[(n0 + g) * SWK + k0 + t + 4]);
                mma8(c + (0 * NTW + nt) * 4, a[0], b);
                mma8(c + (1 * NTW + nt) * 4, a[1], b);
            }
        }
        __syncthreads();
    }
}

// bias + SiLU on accums, rna-tf32 store back to A (hidden layers, NTW=16)
__device__ __forceinline__ void silu_store(
    float* __restrict__ A, const float* __restrict__ bias, const float* c,
    int wm, int wn, int g, int t)
{
#pragma unroll
    for (int mt = 0; mt < 2; mt++) {
        int rA = 32 * wm + 16 * mt + g, rB = rA + 8;
#pragma unroll
        for (int nt = 0; nt < 16; nt++) {
            int col = 128 * wn + 8 * nt + 2 * t;
            const float* cc = c + (mt * 16 + nt) * 4;
            float b0 = __ldg(bias + col), b1 = __ldg(bias + col + 1);
            float v;
            v = cc[0] + b0; v = v / (1.f + __expf(-v)); A[rA * SA + col]     = cvt_rna(v);
            v = cc[1] + b1; v = v / (1.f + __expf(-v)); A[rA * SA + col + 1] = cvt_rna(v);
            v = cc[2] + b0; v = v / (1.f + __expf(-v)); A[rB * SA + col]     = cvt_rna(v);
            v = cc[3] + b1; v = v / (1.f + __expf(-v)); A[rB * SA + col + 1] = cvt_rna(v);
        }
    }
}

// ---------------- fused MLP kernel ----------------
// MODE 0: edge (stage0 = m*(rbf@Wr^T), final N=2);  MODE 1: node (stage0 = g_agg, final N=95)
template<int MODE, int WRF, int NTWF, int NVF>
__global__ void __launch_bounds__(256, 1) fused_mlp(
    const float* __restrict__ m, const float* __restrict__ rbf, const float* __restrict__ Wr,
    const float* __restrict__ lng, const float* __restrict__ lnb,
    const float* __restrict__ bd, float* __restrict__ out, int nrows,
    int up_off, int wd_off, int wf_off)
{
    extern __shared__ float sm[];
    float* A   = sm + F_A;
    float* Wb  = sm + F_WB;
    float* S4  = sm + F_S4;
    float* WrS = sm + F_WR;
    const float* Wup = g_wcvt + up_off;
    const float* Wd  = g_wcvt + wd_off;
    const float* Wf  = g_wcvt + wf_off;

    int tid = threadIdx.x, wid = tid >> 5, lane = tid & 31;
    int wm = wid & 3, wn = wid >> 2, g = lane >> 2, t = lane & 3;
    int row0 = blockIdx.x * 128;

    // ---- stage0: build A[:, 0:128] (rna tf32) ----
    {
        int r = tid & 127, kh = (tid >> 7) * 64;
        if (MODE == 0) {
            for (int i = tid; i < 768; i += 256) WrS[i] = Wr[i];
            __syncthreads();
            const float* rb = rbf + (size_t)(row0 + r) * 6;
            float b0 = rb[0], b1 = rb[1], b2 = rb[2], b3 = rb[3], b4 = rb[4], b5 = rb[5];
            const float* mr = m + (size_t)(row0 + r) * 128;
            for (int k0 = kh; k0 < kh + 64; k0 += 4) {
                float4 mv = *reinterpret_cast<const float4*>(mr + k0);
#pragma unroll
                for (int j = 0; j < 4; j++) {
                    const float* w = WrS + (k0 + j) * 6;
                    float cf = b0*w[0] + b1*w[1] + b2*w[2] + b3*w[3] + b4*w[4] + b5*w[5];
                    float mvj = (j == 0) ? mv.x : (j == 1) ? mv.y : (j == 2) ? mv.z : mv.w;
                    A[r * SA + k0 + j] = cvt_rna(mvj * cf);
                }
            }
        } else {
            bool valid = (row0 + r) < nrows;
            const float* srcp = g_agg + (size_t)(row0 + r) * 128;
            for (int k0 = kh; k0 < kh + 64; k0 += 4) {
                float4 v = valid ? *reinterpret_cast<const float4*>(srcp + k0)
                                 : make_float4(0.f, 0.f, 0.f, 0.f);
                A[r * SA + k0 + 0] = cvt_rna(v.x);
                A[r * SA + k0 + 1] = cvt_rna(v.y);
                A[r * SA + k0 + 2] = cvt_rna(v.z);
                A[r * SA + k0 + 3] = cvt_rna(v.w);
            }
        }
    }
    __syncthreads();

    float c[128];

    // ---- L0: up-projection (K=128) + LayerNorm ----
#pragma unroll
    for (int i = 0; i < 128; i++) c[i] = 0.f;
    gemm_layer<128, 256, 16>(Wup, 256, A, Wb, c, tid, wm, wn, g, t);
    {
        float s[4] = {0.f, 0.f, 0.f, 0.f}, q2[4] = {0.f, 0.f, 0.f, 0.f};
#pragma unroll
        for (int mt = 0; mt < 2; mt++)
#pragma unroll
            for (int nt = 0; nt < 16; nt++) {
                const float* cc = c + (mt * 16 + nt) * 4;
                s[mt*2]   += cc[0] + cc[1]; q2[mt*2]   += cc[0]*cc[0] + cc[1]*cc[1];
                s[mt*2+1] += cc[2] + cc[3]; q2[mt*2+1] += cc[2]*cc[2] + cc[3]*cc[3];
            }
#pragma unroll
        for (int off = 1; off <= 2; off <<= 1)
#pragma unroll
            for (int i = 0; i < 4; i++) {
                s[i]  += __shfl_xor_sync(0xffffffffu, s[i],  off);
                q2[i] += __shfl_xor_sync(0xffffffffu, q2[i], off);
            }
        if (t == 0) {
#pragma unroll
            for (int i = 0; i < 4; i++) {
                int row = 32 * wm + 16 * (i >> 1) + g + 8 * (i & 1);
                S4[row * 4 + wn]     = s[i];
                S4[row * 4 + 2 + wn] = q2[i];
            }
        }
        __syncthreads();
        float mu[4], rs[4];
#pragma unroll
        for (int i = 0; i < 4; i++) {
            int row = 32 * wm + 16 * (i >> 1) + g + 8 * (i & 1);
            float sum = S4[row * 4] + S4[row * 4 + 1];
            float sq  = S4[row * 4 + 2] + S4[row * 4 + 3];
            float m_ = sum * (1.f / 256.f);
            mu[i] = m_;
            rs[i] = rsqrtf(sq * (1.f / 256.f) - m_ * m_ + 1e-5f);
        }
#pragma unroll
        for (int mt = 0; mt < 2; mt++) {
            int rA = 32 * wm + 16 * mt + g, rB = rA + 8;
            int iA = mt * 2, iB = mt * 2 + 1;
#pragma unroll
            for (int nt = 0; nt < 16; nt++) {
                int col = 128 * wn + 8 * nt + 2 * t;
                const float* cc = c + (mt * 16 + nt) * 4;
                float g0 = __ldg(lng + col), g1 = __ldg(lng + col + 1);
                float e0 = __ldg(lnb + col), e1 = __ldg(lnb + col + 1);
                A[rA * SA + col]     = cvt_rna((cc[0] - mu[iA]) * rs[iA] * g0 + e0);
                A[rA * SA + col + 1] = cvt_rna((cc[1] - mu[iA]) * rs[iA] * g1 + e1);
                A[rB * SA + col]     = cvt_rna((cc[2] - mu[iB]) * rs[iB] * g0 + e0);
                A[rB * SA + col + 1] = cvt_rna((cc[3] - mu[iB]) * rs[iB] * g1 + e1);
            }
        }
    }

    // ---- L1..L3: dense 256->256 + SiLU ----
    for (int L = 0; L < 3; L++) {
#pragma unroll
        for (int i = 0; i < 128; i++) c[i] = 0.f;
        gemm_layer<256, 256, 16>(Wd + L * 65536, 256, A, Wb, c, tid, wm, wn, g, t);
        silu_store(A, bd + L * 256, c, wm, wn, g, t);
    }

    // ---- final projection ----
    float cf[2 * NTWF * 4];
#pragma unroll
    for (int i = 0; i < 2 * NTWF * 4; i++) cf[i] = 0.f;
    // zero the padding rows of both W-tile buffers (persist across k-tiles)
    for (int i = tid; i < (WRF - NVF) * 32; i += 256) {
        int n = NVF + i / 32, k = i % 32;
        Wb[n * SWK + k] = 0.f;
        Wb[WRF * SWK + n * SWK + k] = 0.f;
    }
    gemm_layer<256, WRF, NTWF>(Wf, NVF, A, Wb, cf, tid, wm, wn, g, t);

    if (MODE == 0) {
        if (wn == 0 && t == 0) {
#pragma unroll
            for (int mt = 0; mt < 2; mt++) {
                int rA = row0 + 32 * wm + 16 * mt + g, rB = rA + 8;
                out[(size_t)rA * 2 + 0] = cf[mt * NTWF * 4 + 0];
                out[(size_t)rA * 2 + 1] = cf[mt * NTWF * 4 + 1];
                out[(size_t)rB * 2 + 0] = cf[mt * NTWF * 4 + 2];
                out[(size_t)rB * 2 + 1] = cf[mt * NTWF * 4 + 3];
            }
        }
    } else {
#pragma unroll
        for (int mt = 0; mt < 2; mt++) {
            int rA = row0 + 32 * wm + 16 * mt + g, rB = rA + 8;
#pragma unroll
            for (int nt = 0; nt < NTWF; nt++) {
                int col = wn * (NTWF * 8) + nt * 8 + 2 * t;
                const float* cc = cf + (mt * NTWF + nt) * 4;
                if (rA < nrows) {
                    if (col < 95)     out[(size_t)rA * 95 + col]     = cc[0];
                    if (col + 1 < 95) out[(size_t)rA * 95 + col + 1] = cc[1];
                }
                if (rB < nrows) {
                    if (col < 95)     out[(size_t)rB * 95 + col]     = cc[2];
                    if (col + 1 < 95) out[(size_t)rB * 95 + col + 1] = cc[3];
                }
            }
        }
    }
}

// ---------------- weight conversion (fp32 -> rna tf32) ----------------
__global__ void cvt_w(const float* __restrict__ s, int off, int n)
{
    int i = blockIdx.x * 256 + threadIdx.x;
    if (i < n) g_wcvt[off + i] = cvt_rna(s[i]);
}

// ---------------- node scatter ----------------
__global__ void zero_agg_kernel()
{
    size_t n = (size_t)N_TOT * 128;
    for (size_t i = (size_t)blockIdx.x * blockDim.x + threadIdx.x; i < n;
         i += (size_t)gridDim.x * blockDim.x)
        g_agg[i] = 0.f;
}

__global__ void __launch_bounds__(256) scatter_kernel(
    const float* __restrict__ m, const float* __restrict__ rbf,
    const int* __restrict__ src, const float* __restrict__ Wr)
{
    __shared__ float Wrs[128 * 6];
    for (int idx = threadIdx.x; idx < 128 * 6; idx += 256) Wrs[idx] = Wr[idx];
    __syncthreads();
    int sub = threadIdx.x >> 7;
    int k   = threadIdx.x & 127;
    for (long long e = (long long)blockIdx.x * 2 + sub; e < E_TOT;
         e += (long long)gridDim.x * 2) {
        const float* rb = rbf + e * 6;
        float r0 = __ldg(rb+0), r1 = __ldg(rb+1), r2 = __ldg(rb+2);
        float r3 = __ldg(rb+3), r4 = __ldg(rb+4), r5 = __ldg(rb+5);
        const float* wr = Wrs + k * 6;
        float cc = r0*wr[0] + r1*wr[1] + r2*wr[2] + r3*wr[3] + r4*wr[4] + r5*wr[5];
        float v = m[(size_t)e * 128 + k] * cc;
        int s = __ldg(src + e);
        atomicAdd(g_agg + (size_t)s * 128 + k, v);
    }
}

// ---------------- launch ----------------
extern "C" void kernel_launch(void* const* d_in, const int* in_sizes, int n_in,
                              void* d_out, int out_size)
{
    const float* m       = (const float*)d_in[0];
    const float* rbf     = (const float*)d_in[1];
    const int*   src     = (const int*)  d_in[2];
    const float* W_rbf_e = (const float*)d_in[3];
    const float* W_up_e  = (const float*)d_in[4];
    const float* ln_g_e  = (const float*)d_in[5];
    const float* ln_b_e  = (const float*)d_in[6];
    const float* Wd_e    = (const float*)d_in[7];
    const float* bd_e    = (const float*)d_in[8];
    const float* W_fin_e = (const float*)d_in[9];
    const float* W_rbf_n = (const float*)d_in[10];
    const float* W_up_n  = (const float*)d_in[11];
    const float* ln_g_n  = (const float*)d_in[12];
    const float* ln_b_n  = (const float*)d_in[13];
    const float* Wd_n    = (const float*)d_in[14];
    const float* bd_n    = (const float*)d_in[15];
    const float* W_fin_n = (const float*)d_in[16];

    float* edge_out = (float*)d_out;
    float* node_out = (float*)d_out + (size_t)E_TOT * 2;

    cudaFuncSetAttribute((const void*)fused_mlp<0, 16, 1, 2>,
                         cudaFuncAttributeMaxDynamicSharedMemorySize, SMEM_BYTES);
    cudaFuncSetAttribute((const void*)fused_mlp<1, 96, 6, 95>,
                         cudaFuncAttributeMaxDynamicSharedMemorySize, SMEM_BYTES);

    // convert all weights to rna-tf32 once
    cvt_w<<<(32768 + 255) / 256, 256>>>(W_up_e,  OFF_UP_E, 32768);
    cvt_w<<<(196608 + 255) / 256, 256>>>(Wd_e,   OFF_WD_E, 196608);
    cvt_w<<<(512 + 255) / 256, 256>>>(W_fin_e,   OFF_WF_E, 512);
    cvt_w<<<(32768 + 255) / 256, 256>>>(W_up_n,  OFF_UP_N, 32768);
    cvt_w<<<(196608 + 255) / 256, 256>>>(Wd_n,   OFF_WD_N, 196608);
    cvt_w<<<(24320 + 255) / 256, 256>>>(W_fin_n, OFF_WF_N, 24320);

    zero_agg_kernel<<<512, 256>>>();
    scatter_kernel<<<1184, 256>>>(m, rbf, src, W_rbf_n);

    fused_mlp<0, 16, 1, 2><<<E_TOT / 128, 256, SMEM_BYTES>>>(
        m, rbf, W_rbf_e, ln_g_e, ln_b_e, bd_e, edge_out, E_TOT,
        OFF_UP_E, OFF_WD_E, OFF_WF_E);
    fused_mlp<1, 96, 6, 95><<<(N_TOT + 127) / 128, 256, SMEM_BYTES>>>(
        nullptr, nullptr, nullptr, ln_g_n, ln_b_n, bd_n, node_out, N_TOT,
        OFF_UP_N, OFF_WD_N, OFF_WF_N);
}

// round 4
// speedup vs baseline: 5.2938x; 1.4801x over previous
#include <cuda_runtime.h>
#include <cuda_fp16.h>
#include <math.h>
#include <stdint.h>

#define E_TOT 480000
#define N_TOT 30000

constexpr int SA_H = 264;  // A row stride in halves (528B: 16B-aligned, ldmatrix conflict-free)
constexpr int SW_H = 72;   // W tile row stride in halves (144B)

// smem (bytes)
#define B_A    0                         // 128 x 264 halves = 67584
#define B_WB   67584                     // 2 x 256 x 72 halves = 73728
#define B_S4   141312                    // 128 x 4 floats = 2048
#define B_WR   143360                    // 128 x 6 floats = 3072
#define SMEM_BYTES 146432

__device__ float g_agg[(size_t)N_TOT * 128];

// fp16-converted weights: per branch [up 32768][wd 196608][fin ...]
#define EOFF 0
#define NOFF 229888
__device__ __align__(16) __half g_wh[483584];

// ---------------- helpers ----------------
__device__ __forceinline__ uint32_t smem_u32(const void* p) {
    uint32_t a;
    asm("{ .reg .u64 t; cvta.to.shared.u64 t, %1; cvt.u32.u64 %0, t; }" : "=r"(a) : "l"(p));
    return a;
}
__device__ __forceinline__ void cpa16(uint32_t s, const void* g) {
    asm volatile("cp.async.cg.shared.global [%0], [%1], 16;" :: "r"(s), "l"(g));
}
#define LDSM_X4(r0, r1, r2, r3, a) \
    asm volatile("ldmatrix.sync.aligned.m8n8.x4.shared.b16 {%0,%1,%2,%3}, [%4];" \
        : "=r"(r0), "=r"(r1), "=r"(r2), "=r"(r3) : "r"(a))
#define LDSM_X2(r0, r1, a) \
    asm volatile("ldmatrix.sync.aligned.m8n8.x2.shared.b16 {%0,%1}, [%2];" \
        : "=r"(r0), "=r"(r1) : "r"(a))
__device__ __forceinline__ void mma16(float* c, const uint32_t a[4], uint32_t b0, uint32_t b1) {
    asm volatile("mma.sync.aligned.m16n8k16.row.col.f32.f16.f16.f32 "
        "{%0,%1,%2,%3},{%4,%5,%6,%7},{%8,%9},{%0,%1,%2,%3};"
        : "+f"(c[0]), "+f"(c[1]), "+f"(c[2]), "+f"(c[3])
        : "r"(a[0]), "r"(a[1]), "r"(a[2]), "r"(a[3]), "r"(b0), "r"(b1));
}

// GEMM: C[128, wn-split] += A[128,K](fp16 smem) @ W[wrows,K]^T (fp16 global, streamed)
// warps: wm = wid&3 (32 rows), wn = wid>>2 (NTW*8 cols each). k-tile = 64.
template<int K, int WR, int NTW>
__device__ __forceinline__ void gemm16(
    const __half* __restrict__ Wg, int wrows,
    const __half* As, __half* Wb, float* c,
    int tid, int lane, int wm, int wn)
{
    constexpr int NT = K / 64;
    int mq = lane >> 3, lr = lane & 7;

    for (int idx = tid; idx < WR * 8; idx += 256) {
        int n = idx >> 3, q = idx & 7;
        if (n < wrows)
            cpa16(smem_u32(Wb + n * SW_H + q * 8), Wg + (size_t)n * K + q * 8);
    }
    asm volatile("cp.async.commit_group;");

    for (int kt = 0; kt < NT; kt++) {
        const __half* cur = Wb + (kt & 1) * (WR * SW_H);
        if (kt + 1 < NT) {
            __half* nxt = Wb + ((kt + 1) & 1) * (WR * SW_H);
            for (int idx = tid; idx < WR * 8; idx += 256) {
                int n = idx >> 3, q = idx & 7;
                if (n < wrows)
                    cpa16(smem_u32(nxt + n * SW_H + q * 8),
                          Wg + (size_t)n * K + (kt + 1) * 64 + q * 8);
            }
            asm volatile("cp.async.commit_group;");
            asm volatile("cp.async.wait_group 1;");
        } else {
            asm volatile("cp.async.wait_group 0;");
        }
        __syncthreads();
#pragma unroll
        for (int ks = 0; ks < 4; ks++) {
            uint32_t a0[4], a1[4];
            // A mats: (m0,k0)(m8,k0)(m0,k8)(m8,k8) -> m_off=(mq&1)*8, k_off=(mq>>1)*8
            uint32_t aad0 = smem_u32(As + (32 * wm + (mq & 1) * 8 + lr) * SA_H
                                        + kt * 64 + ks * 16 + (mq >> 1) * 8);
            LDSM_X4(a0[0], a0[1], a0[2], a0[3], aad0);
            uint32_t aad1 = aad0 + 16 * SA_H * 2;
            LDSM_X4(a1[0], a1[1], a1[2], a1[3], aad1);
#pragma unroll
            for (int p = 0; p < NTW / 2; p++) {
                // B mats: (n0,k0)(n0,k8)(n8,k0)(n8,k8) -> n_off=(mq>>1)*8, k_off=(mq&1)*8
                uint32_t b0, b1, b2, b3;
                uint32_t bad = smem_u32(cur + (wn * (NTW * 8) + p * 16 + (mq >> 1) * 8 + lr) * SW_H
                                            + ks * 16 + (mq & 1) * 8);
                LDSM_X4(b0, b1, b2, b3, bad);
                mma16(c + (0 * NTW + 2 * p) * 4,     a0, b0, b1);
                mma16(c + (1 * NTW + 2 * p) * 4,     a1, b0, b1);
                mma16(c + (0 * NTW + 2 * p + 1) * 4, a0, b2, b3);
                mma16(c + (1 * NTW + 2 * p + 1) * 4, a1, b2, b3);
            }
            if (NTW & 1) {
                int i = lane & 15;
                uint32_t b0, b1;
                uint32_t bad = smem_u32(cur + (wn * (NTW * 8) + (NTW - 1) * 8 + (i & 7)) * SW_H
                                            + ks * 16 + (i >> 3) * 8);
                LDSM_X2(b0, b1, bad);
                mma16(c + (0 * NTW + NTW - 1) * 4, a0, b0, b1);
                mma16(c + (1 * NTW + NTW - 1) * 4, a1, b0, b1);
            }
        }
        __syncthreads();
    }
}

// bias + SiLU, store fp16 back to A (hidden layers, NTW=16)
__device__ __forceinline__ void silu_store(
    __half* __restrict__ A, const float* __restrict__ bias, const float* c,
    int wm, int wn, int g, int t)
{
#pragma unroll
    for (int mt = 0; mt < 2; mt++) {
        int rA = 32 * wm + 16 * mt + g, rB = rA + 8;
#pragma unroll
        for (int nt = 0; nt < 16; nt++) {
            int col = 128 * wn + 8 * nt + 2 * t;
            const float* cc = c + (mt * 16 + nt) * 4;
            float b0 = __ldg(bias + col), b1 = __ldg(bias + col + 1);
            float v0 = cc[0] + b0; v0 = v0 / (1.f + __expf(-v0));
            float v1 = cc[1] + b1; v1 = v1 / (1.f + __expf(-v1));
            float v2 = cc[2] + b0; v2 = v2 / (1.f + __expf(-v2));
            float v3 = cc[3] + b1; v3 = v3 / (1.f + __expf(-v3));
            *reinterpret_cast<__half2*>(A + rA * SA_H + col) = __floats2half2_rn(v0, v1);
            *reinterpret_cast<__half2*>(A + rB * SA_H + col) = __floats2half2_rn(v2, v3);
        }
    }
}

// ---------------- fused MLP (fp16 tensor cores) ----------------
template<int MODE, int WRF, int NTWF, int NVF>
__global__ void __launch_bounds__(256, 1) fused_mlp16(
    const float* __restrict__ m, const float* __restrict__ rbf, const float* __restrict__ Wr,
    const float* __restrict__ lng, const float* __restrict__ lnb,
    const float* __restrict__ bd, float* __restrict__ out, int nrows,
    int up_off, int wd_off, int wf_off)
{
    extern __shared__ unsigned char smraw[];
    __half* A   = reinterpret_cast<__half*>(smraw + B_A);
    __half* Wb  = reinterpret_cast<__half*>(smraw + B_WB);
    float*  S4  = reinterpret_cast<float*>(smraw + B_S4);
    float*  WrS = reinterpret_cast<float*>(smraw + B_WR);
    const __half* Wup = g_wh + up_off;
    const __half* Wd  = g_wh + wd_off;
    const __half* Wf  = g_wh + wf_off;

    int tid = threadIdx.x, wid = tid >> 5, lane = tid & 31;
    int wm = wid & 3, wn = wid >> 2, g = lane >> 2, t = lane & 3;
    int row0 = blockIdx.x * 128;

    // ---- stage0: A[:, 0:128] fp16 ----
    {
        int r = tid & 127, kh = (tid >> 7) * 64;
        if (MODE == 0) {
            for (int i = tid; i < 768; i += 256) WrS[i] = Wr[i];
            __syncthreads();
            const float* rb = rbf + (size_t)(row0 + r) * 6;
            float b0 = rb[0], b1 = rb[1], b2 = rb[2], b3 = rb[3], b4 = rb[4], b5 = rb[5];
            const float* mr = m + (size_t)(row0 + r) * 128;
            for (int k0 = kh; k0 < kh + 64; k0 += 4) {
                float4 mv = *reinterpret_cast<const float4*>(mr + k0);
                float cf[4];
#pragma unroll
                for (int j = 0; j < 4; j++) {
                    const float* w = WrS + (k0 + j) * 6;
                    cf[j] = b0*w[0] + b1*w[1] + b2*w[2] + b3*w[3] + b4*w[4] + b5*w[5];
                }
                *reinterpret_cast<__half2*>(A + r * SA_H + k0)     = __floats2half2_rn(mv.x * cf[0], mv.y * cf[1]);
                *reinterpret_cast<__half2*>(A + r * SA_H + k0 + 2) = __floats2half2_rn(mv.z * cf[2], mv.w * cf[3]);
            }
        } else {
            int r2 = tid & 127;
            bool valid = (row0 + r2) < nrows;
            const float* srcp = g_agg + (size_t)(row0 + r2) * 128;
            for (int k0 = kh; k0 < kh + 64; k0 += 4) {
                float4 v = valid ? *reinterpret_cast<const float4*>(srcp + k0)
                                 : make_float4(0.f, 0.f, 0.f, 0.f);
                *reinterpret_cast<__half2*>(A + r2 * SA_H + k0)     = __floats2half2_rn(v.x, v.y);
                *reinterpret_cast<__half2*>(A + r2 * SA_H + k0 + 2) = __floats2half2_rn(v.z, v.w);
            }
        }
    }
    __syncthreads();

    float c[128];

    // ---- L0: up (K=128) + LayerNorm ----
#pragma unroll
    for (int i = 0; i < 128; i++) c[i] = 0.f;
    gemm16<128, 256, 16>(Wup, 256, A, Wb, c, tid, lane, wm, wn);
    {
        float s[4] = {0.f, 0.f, 0.f, 0.f}, q2[4] = {0.f, 0.f, 0.f, 0.f};
#pragma unroll
        for (int mt = 0; mt < 2; mt++)
#pragma unroll
            for (int nt = 0; nt < 16; nt++) {
                const float* cc = c + (mt * 16 + nt) * 4;
                s[mt*2]   += cc[0] + cc[1]; q2[mt*2]   += cc[0]*cc[0] + cc[1]*cc[1];
                s[mt*2+1] += cc[2] + cc[3]; q2[mt*2+1] += cc[2]*cc[2] + cc[3]*cc[3];
            }
#pragma unroll
        for (int off = 1; off <= 2; off <<= 1)
#pragma unroll
            for (int i = 0; i < 4; i++) {
                s[i]  += __shfl_xor_sync(0xffffffffu, s[i],  off);
                q2[i] += __shfl_xor_sync(0xffffffffu, q2[i], off);
            }
        if (t == 0) {
#pragma unroll
            for (int i = 0; i < 4; i++) {
                int row = 32 * wm + 16 * (i >> 1) + g + 8 * (i & 1);
                S4[row * 4 + wn]     = s[i];
                S4[row * 4 + 2 + wn] = q2[i];
            }
        }
        __syncthreads();
        float mu[4], rs[4];
#pragma unroll
        for (int i = 0; i < 4; i++) {
            int row = 32 * wm + 16 * (i >> 1) + g + 8 * (i & 1);
            float sum = S4[row * 4] + S4[row * 4 + 1];
            float sq  = S4[row * 4 + 2] + S4[row * 4 + 3];
            float m_ = sum * (1.f / 256.f);
            mu[i] = m_;
            rs[i] = rsqrtf(sq * (1.f / 256.f) - m_ * m_ + 1e-5f);
        }
#pragma unroll
        for (int mt = 0; mt < 2; mt++) {
            int rA = 32 * wm + 16 * mt + g, rB = rA + 8;
            int iA = mt * 2, iB = mt * 2 + 1;
#pragma unroll
            for (int nt = 0; nt < 16; nt++) {
                int col = 128 * wn + 8 * nt + 2 * t;
                const float* cc = c + (mt * 16 + nt) * 4;
                float g0 = __ldg(lng + col), g1 = __ldg(lng + col + 1);
                float e0 = __ldg(lnb + col), e1 = __ldg(lnb + col + 1);
                *reinterpret_cast<__half2*>(A + rA * SA_H + col) =
                    __floats2half2_rn((cc[0] - mu[iA]) * rs[iA] * g0 + e0,
                                      (cc[1] - mu[iA]) * rs[iA] * g1 + e1);
                *reinterpret_cast<__half2*>(A + rB * SA_H + col) =
                    __floats2half2_rn((cc[2] - mu[iB]) * rs[iB] * g0 + e0,
                                      (cc[3] - mu[iB]) * rs[iB] * g1 + e1);
            }
        }
    }

    // ---- L1..L3 dense + SiLU ----
    for (int L = 0; L < 3; L++) {
#pragma unroll
        for (int i = 0; i < 128; i++) c[i] = 0.f;
        gemm16<256, 256, 16>(Wd + L * 65536, 256, A, Wb, c, tid, lane, wm, wn);
        silu_store(A, bd + L * 256, c, wm, wn, g, t);
    }

    // ---- final projection ----
    float cf[2 * NTWF * 4];
#pragma unroll
    for (int i = 0; i < 2 * NTWF * 4; i++) cf[i] = 0.f;
    for (int i = tid; i < (WRF - NVF) * 64; i += 256) {
        int n = NVF + i / 64, k = i % 64;
        Wb[n * SW_H + k] = __float2half(0.f);
        Wb[WRF * SW_H + n * SW_H + k] = __float2half(0.f);
    }
    gemm16<256, WRF, NTWF>(Wf, NVF, A, Wb, cf, tid, lane, wm, wn);

    if (MODE == 0) {
        if (wn == 0 && t == 0) {
#pragma unroll
            for (int mt = 0; mt < 2; mt++) {
                int rA = row0 + 32 * wm + 16 * mt + g, rB = rA + 8;
                out[(size_t)rA * 2 + 0] = cf[mt * NTWF * 4 + 0];
                out[(size_t)rA * 2 + 1] = cf[mt * NTWF * 4 + 1];
                out[(size_t)rB * 2 + 0] = cf[mt * NTWF * 4 + 2];
                out[(size_t)rB * 2 + 1] = cf[mt * NTWF * 4 + 3];
            }
        }
    } else {
#pragma unroll
        for (int mt = 0; mt < 2; mt++) {
            int rA = row0 + 32 * wm + 16 * mt + g, rB = rA + 8;
#pragma unroll
            for (int nt = 0; nt < NTWF; nt++) {
                int col = wn * (NTWF * 8) + nt * 8 + 2 * t;
                const float* cc = cf + (mt * NTWF + nt) * 4;
                if (rA < nrows) {
                    if (col < 95)     out[(size_t)rA * 95 + col]     = cc[0];
                    if (col + 1 < 95) out[(size_t)rA * 95 + col + 1] = cc[1];
                }
                if (rB < nrows) {
                    if (col < 95)     out[(size_t)rB * 95 + col]     = cc[2];
                    if (col + 1 < 95) out[(size_t)rB * 95 + col + 1] = cc[3];
                }
            }
        }
    }
}

// ---------------- weight conversion fp32 -> fp16 ----------------
__global__ void cvt_branch(const float* __restrict__ up, const float* __restrict__ wd,
                           const float* __restrict__ fin, int fin_n, int base)
{
    int i = blockIdx.x * 256 + threadIdx.x;
    if (i < 32768)                 g_wh[base + i] = __float2half_rn(up[i]);
    else if (i < 229376)           g_wh[base + i] = __float2half_rn(wd[i - 32768]);
    else if (i < 229376 + fin_n)   g_wh[base + i] = __float2half_rn(fin[i - 229376]);
}

// ---------------- node scatter ----------------
__global__ void zero_agg_kernel()
{
    size_t n = (size_t)N_TOT * 128;
    for (size_t i = (size_t)blockIdx.x * blockDim.x + threadIdx.x; i < n;
         i += (size_t)gridDim.x * blockDim.x)
        g_agg[i] = 0.f;
}

__global__ void __launch_bounds__(256) scatter_kernel(
    const float* __restrict__ m, const float* __restrict__ rbf,
    const int* __restrict__ src, const float* __restrict__ Wr)
{
    __shared__ float Wrs[128 * 6];
    for (int idx = threadIdx.x; idx < 128 * 6; idx += 256) Wrs[idx] = Wr[idx];
    __syncthreads();
    int sub = threadIdx.x >> 7;
    int k   = threadIdx.x & 127;
    for (long long e = (long long)blockIdx.x * 2 + sub; e < E_TOT;
         e += (long long)gridDim.x * 2) {
        const float* rb = rbf + e * 6;
        float r0 = __ldg(rb+0), r1 = __ldg(rb+1), r2 = __ldg(rb+2);
        float r3 = __ldg(rb+3), r4 = __ldg(rb+4), r5 = __ldg(rb+5);
        const float* wr = Wrs + k * 6;
        float cc = r0*wr[0] + r1*wr[1] + r2*wr[2] + r3*wr[3] + r4*wr[4] + r5*wr[5];
        float v = m[(size_t)e * 128 + k] * cc;
        int s = __ldg(src + e);
        atomicAdd(g_agg + (size_t)s * 128 + k, v);
    }
}

// ---------------- launch ----------------
extern "C" void kernel_launch(void* const* d_in, const int* in_sizes, int n_in,
                              void* d_out, int out_size)
{
    const float* m       = (const float*)d_in[0];
    const float* rbf     = (const float*)d_in[1];
    const int*   src     = (const int*)  d_in[2];
    const float* W_rbf_e = (const float*)d_in[3];
    const float* W_up_e  = (const float*)d_in[4];
    const float* ln_g_e  = (const float*)d_in[5];
    const float* ln_b_e  = (const float*)d_in[6];
    const float* Wd_e    = (const float*)d_in[7];
    const float* bd_e    = (const float*)d_in[8];
    const float* W_fin_e = (const float*)d_in[9];
    const float* W_rbf_n = (const float*)d_in[10];
    const float* W_up_n  = (const float*)d_in[11];
    const float* ln_g_n  = (const float*)d_in[12];
    const float* ln_b_n  = (const float*)d_in[13];
    const float* Wd_n    = (const float*)d_in[14];
    const float* bd_n    = (const float*)d_in[15];
    const float* W_fin_n = (const float*)d_in[16];

    float* edge_out = (float*)d_out;
    float* node_out = (float*)d_out + (size_t)E_TOT * 2;

    cudaFuncSetAttribute((const void*)fused_mlp16<0, 16, 1, 2>,
                         cudaFuncAttributeMaxDynamicSharedMemorySize, SMEM_BYTES);
    cudaFuncSetAttribute((const void*)fused_mlp16<1, 96, 6, 95>,
                         cudaFuncAttributeMaxDynamicSharedMemorySize, SMEM_BYTES);

    // launch order chosen so launch index 5 (ncu -s 5 -c 1) = edge kernel
    cvt_branch<<<(229888 + 255) / 256, 256>>>(W_up_e, Wd_e, W_fin_e, 512,   EOFF);   // 0
    cvt_branch<<<(253696 + 255) / 256, 256>>>(W_up_n, Wd_n, W_fin_n, 24320, NOFF);   // 1
    zero_agg_kernel<<<512, 256>>>();                                                  // 2
    scatter_kernel<<<1184, 256>>>(m, rbf, src, W_rbf_n);                              // 3
    fused_mlp16<1, 96, 6, 95><<<(N_TOT + 127) / 128, 256, SMEM_BYTES>>>(              // 4
        nullptr, nullptr, nullptr, ln_g_n, ln_b_n, bd_n, node_out, N_TOT,
        NOFF, NOFF + 32768, NOFF + 229376);
    fused_mlp16<0, 16, 1, 2><<<E_TOT / 128, 256, SMEM_BYTES>>>(                       // 5
        m, rbf, W_rbf_e, ln_g_e, ln_b_e, bd_e, edge_out, E_TOT,
        EOFF, EOFF + 32768, EOFF + 229376);
}

// round 5
// speedup vs baseline: 6.5683x; 1.2408x over previous
#include <cuda_runtime.h>
#include <cuda_fp16.h>
#include <math.h>
#include <stdint.h>

#define E_TOT 480000
#define N_TOT 30000
#define EB 7500   // edge blocks (64 rows each)
#define NB 469    // node blocks

constexpr int SA_H = 264;  // A row stride (halves) -> 528B, ldmatrix conflict-free
constexpr int SW_H = 72;   // W tile row stride (halves) -> 144B

// smem (bytes): A 64x264x2=33792 | Wb 2x256x72x2=73728 | S4 64x8 f32=2048 | WrS 768 f32=3072
#define B_A    0
#define B_WB   33792
#define B_S4   107520
#define B_WR   109568
#define SMEM_BYTES 112640

__device__ float g_agg[(size_t)N_TOT * 128];
#define EOFF 0
#define NOFF 229888
__device__ __align__(16) __half g_wh[483584];

// ---------------- helpers ----------------
__device__ __forceinline__ uint32_t smem_u32(const void* p) {
    uint32_t a;
    asm("{ .reg .u64 t; cvta.to.shared.u64 t, %1; cvt.u32.u64 %0, t; }" : "=r"(a) : "l"(p));
    return a;
}
__device__ __forceinline__ void cpa16(uint32_t s, const void* g) {
    asm volatile("cp.async.cg.shared.global [%0], [%1], 16;" :: "r"(s), "l"(g));
}
#define LDSM_X4(r0, r1, r2, r3, a) \
    asm volatile("ldmatrix.sync.aligned.m8n8.x4.shared.b16 {%0,%1,%2,%3}, [%4];" \
        : "=r"(r0), "=r"(r1), "=r"(r2), "=r"(r3) : "r"(a))
#define LDSM_X2(r0, r1, a) \
    asm volatile("ldmatrix.sync.aligned.m8n8.x2.shared.b16 {%0,%1}, [%2];" \
        : "=r"(r0), "=r"(r1) : "r"(a))
__device__ __forceinline__ void mma16(float* c, const uint32_t a[4], uint32_t b0, uint32_t b1) {
    asm volatile("mma.sync.aligned.m16n8k16.row.col.f32.f16.f16.f32 "
        "{%0,%1,%2,%3},{%4,%5,%6,%7},{%8,%9},{%0,%1,%2,%3};"
        : "+f"(c[0]), "+f"(c[1]), "+f"(c[2]), "+f"(c[3])
        : "r"(a[0]), "r"(a[1]), "r"(a[2]), "r"(a[3]), "r"(b0), "r"(b1));
}

// GEMM: C[64, 8*NTW*4] += A[64,K](fp16 smem) @ W[wrows,K]^T  (warps 2M x 4N)
template<int K, int WR, int NTW>
__device__ __forceinline__ void gemm16(
    const __half* __restrict__ Wg, int wrows,
    const __half* As, __half* Wb, float* c,
    int tid, int lane, int wm, int wn)
{
    constexpr int NT = K / 64;
    int mq = lane >> 3, lr = lane & 7;

    for (int idx = tid; idx < WR * 8; idx += 256) {
        int n = idx >> 3, q = idx & 7;
        if (n < wrows)
            cpa16(smem_u32(Wb + n * SW_H + q * 8), Wg + (size_t)n * K + q * 8);
    }
    asm volatile("cp.async.commit_group;");

    for (int kt = 0; kt < NT; kt++) {
        const __half* cur = Wb + (kt & 1) * (WR * SW_H);
        if (kt + 1 < NT) {
            __half* nxt = Wb + ((kt + 1) & 1) * (WR * SW_H);
            for (int idx = tid; idx < WR * 8; idx += 256) {
                int n = idx >> 3, q = idx & 7;
                if (n < wrows)
                    cpa16(smem_u32(nxt + n * SW_H + q * 8),
                          Wg + (size_t)n * K + (kt + 1) * 64 + q * 8);
            }
            asm volatile("cp.async.commit_group;");
            asm volatile("cp.async.wait_group 1;");
        } else {
            asm volatile("cp.async.wait_group 0;");
        }
        __syncthreads();
#pragma unroll
        for (int ks = 0; ks < 4; ks++) {
            uint32_t a0[4], a1[4];
            uint32_t aad0 = smem_u32(As + (32 * wm + (mq & 1) * 8 + lr) * SA_H
                                        + kt * 64 + ks * 16 + (mq >> 1) * 8);
            LDSM_X4(a0[0], a0[1], a0[2], a0[3], aad0);
            LDSM_X4(a1[0], a1[1], a1[2], a1[3], aad0 + 16 * SA_H * 2);
#pragma unroll
            for (int p = 0; p < NTW / 2; p++) {
                uint32_t b0, b1, b2, b3;
                uint32_t bad = smem_u32(cur + (wn * (NTW * 8) + p * 16 + (mq >> 1) * 8 + lr) * SW_H
                                            + ks * 16 + (mq & 1) * 8);
                LDSM_X4(b0, b1, b2, b3, bad);
                mma16(c + (0 * NTW + 2 * p) * 4,     a0, b0, b1);
                mma16(c + (1 * NTW + 2 * p) * 4,     a1, b0, b1);
                mma16(c + (0 * NTW + 2 * p + 1) * 4, a0, b2, b3);
                mma16(c + (1 * NTW + 2 * p + 1) * 4, a1, b2, b3);
            }
            if (NTW & 1) {
                int i = lane & 15;
                uint32_t b0, b1;
                uint32_t bad = smem_u32(cur + (wn * (NTW * 8) + (NTW - 1) * 8 + (i & 7)) * SW_H
                                            + ks * 16 + (i >> 3) * 8);
                LDSM_X2(b0, b1, bad);
                mma16(c + (0 * NTW + NTW - 1) * 4, a0, b0, b1);
                mma16(c + (1 * NTW + NTW - 1) * 4, a1, b0, b1);
            }
        }
        __syncthreads();
    }
}

// ---------------- fused MLP body (64-row tile) ----------------
template<int MODE, int WRF, int NTWF, int NVF>
__device__ __forceinline__ void mlp_body(
    int row0,
    const float* __restrict__ m, const float* __restrict__ rbf, const float* __restrict__ Wr,
    const float* __restrict__ lng, const float* __restrict__ lnb,
    const float* __restrict__ bd,
    const __half* __restrict__ Wup, const __half* __restrict__ Wd, const __half* __restrict__ Wf,
    float* __restrict__ out, int nrows, unsigned char* smraw)
{
    __half* A   = reinterpret_cast<__half*>(smraw + B_A);
    __half* Wb  = reinterpret_cast<__half*>(smraw + B_WB);
    float*  S4  = reinterpret_cast<float*>(smraw + B_S4);
    float*  WrS = reinterpret_cast<float*>(smraw + B_WR);

    int tid = threadIdx.x, wid = tid >> 5, lane = tid & 31;
    int wm = wid & 1, wn = wid >> 1, g = lane >> 2, t = lane & 3;

    // ---- stage0: A[64, 0:128] fp16 ----
    {
        int r = tid >> 2, kh = (tid & 3) * 32;
        if (MODE == 0) {
            for (int i = tid; i < 768; i += 256) WrS[i] = Wr[i];
            __syncthreads();
            const float* rb = rbf + (size_t)(row0 + r) * 6;
            float b0 = rb[0], b1 = rb[1], b2 = rb[2], b3 = rb[3], b4 = rb[4], b5 = rb[5];
            const float* mr = m + (size_t)(row0 + r) * 128;
            for (int k0 = kh; k0 < kh + 32; k0 += 4) {
                float4 mv = *reinterpret_cast<const float4*>(mr + k0);
                float cf[4];
#pragma unroll
                for (int j = 0; j < 4; j++) {
                    const float* w = WrS + (k0 + j) * 6;
                    cf[j] = b0*w[0] + b1*w[1] + b2*w[2] + b3*w[3] + b4*w[4] + b5*w[5];
                }
                *reinterpret_cast<__half2*>(A + r * SA_H + k0)     = __floats2half2_rn(mv.x * cf[0], mv.y * cf[1]);
                *reinterpret_cast<__half2*>(A + r * SA_H + k0 + 2) = __floats2half2_rn(mv.z * cf[2], mv.w * cf[3]);
            }
        } else {
            bool valid = (row0 + r) < nrows;
            const float* srcp = g_agg + (size_t)(row0 + r) * 128;
            for (int k0 = kh; k0 < kh + 32; k0 += 4) {
                float4 v = valid ? *reinterpret_cast<const float4*>(srcp + k0)
                                 : make_float4(0.f, 0.f, 0.f, 0.f);
                *reinterpret_cast<__half2*>(A + r * SA_H + k0)     = __floats2half2_rn(v.x, v.y);
                *reinterpret_cast<__half2*>(A + r * SA_H + k0 + 2) = __floats2half2_rn(v.z, v.w);
            }
        }
    }
    __syncthreads();

    float c[64];

    // ---- L0: up (K=128) + LayerNorm ----
#pragma unroll
    for (int i = 0; i < 64; i++) c[i] = 0.f;
    gemm16<128, 256, 8>(Wup, 256, A, Wb, c, tid, lane, wm, wn);
    {
        float s[4] = {0.f, 0.f, 0.f, 0.f}, q2[4] = {0.f, 0.f, 0.f, 0.f};
#pragma unroll
        for (int mt = 0; mt < 2; mt++)
#pragma unroll
            for (int nt = 0; nt < 8; nt++) {
                const float* cc = c + (mt * 8 + nt) * 4;
                s[mt*2]   += cc[0] + cc[1]; q2[mt*2]   += cc[0]*cc[0] + cc[1]*cc[1];
                s[mt*2+1] += cc[2] + cc[3]; q2[mt*2+1] += cc[2]*cc[2] + cc[3]*cc[3];
            }
#pragma unroll
        for (int off = 1; off <= 2; off <<= 1)
#pragma unroll
            for (int i = 0; i < 4; i++) {
                s[i]  += __shfl_xor_sync(0xffffffffu, s[i],  off);
                q2[i] += __shfl_xor_sync(0xffffffffu, q2[i], off);
            }
        if (t == 0) {
#pragma unroll
            for (int i = 0; i < 4; i++) {
                int row = 32 * wm + 16 * (i >> 1) + g + 8 * (i & 1);
                S4[row * 8 + wn]     = s[i];
                S4[row * 8 + 4 + wn] = q2[i];
            }
        }
        __syncthreads();
        float mu[4], rs[4];
#pragma unroll
        for (int i = 0; i < 4; i++) {
            int row = 32 * wm + 16 * (i >> 1) + g + 8 * (i & 1);
            float sum = S4[row*8+0] + S4[row*8+1] + S4[row*8+2] + S4[row*8+3];
            float sq  = S4[row*8+4] + S4[row*8+5] + S4[row*8+6] + S4[row*8+7];
            float m_ = sum * (1.f / 256.f);
            mu[i] = m_;
            rs[i] = rsqrtf(sq * (1.f / 256.f) - m_ * m_ + 1e-5f);
        }
#pragma unroll
        for (int mt = 0; mt < 2; mt++) {
            int rA = 32 * wm + 16 * mt + g, rB = rA + 8;
            int iA = mt * 2, iB = mt * 2 + 1;
#pragma unroll
            for (int nt = 0; nt < 8; nt++) {
                int col = 64 * wn + 8 * nt + 2 * t;
                const float* cc = c + (mt * 8 + nt) * 4;
                float g0 = __ldg(lng + col), g1 = __ldg(lng + col + 1);
                float e0 = __ldg(lnb + col), e1 = __ldg(lnb + col + 1);
                *reinterpret_cast<__half2*>(A + rA * SA_H + col) =
                    __floats2half2_rn((cc[0] - mu[iA]) * rs[iA] * g0 + e0,
                                      (cc[1] - mu[iA]) * rs[iA] * g1 + e1);
                *reinterpret_cast<__half2*>(A + rB * SA_H + col) =
                    __floats2half2_rn((cc[2] - mu[iB]) * rs[iB] * g0 + e0,
                                      (cc[3] - mu[iB]) * rs[iB] * g1 + e1);
            }
        }
    }

    // ---- L1..L3 dense + SiLU ----
    for (int L = 0; L < 3; L++) {
#pragma unroll
        for (int i = 0; i < 64; i++) c[i] = 0.f;
        gemm16<256, 256, 8>(Wd + L * 65536, 256, A, Wb, c, tid, lane, wm, wn);
        const float* bias = bd + L * 256;
#pragma unroll
        for (int mt = 0; mt < 2; mt++) {
            int rA = 32 * wm + 16 * mt + g, rB = rA + 8;
#pragma unroll
            for (int nt = 0; nt < 8; nt++) {
                int col = 64 * wn + 8 * nt + 2 * t;
                const float* cc = c + (mt * 8 + nt) * 4;
                float b0 = __ldg(bias + col), b1 = __ldg(bias + col + 1);
                float v0 = cc[0] + b0; v0 = v0 / (1.f + __expf(-v0));
                float v1 = cc[1] + b1; v1 = v1 / (1.f + __expf(-v1));
                float v2 = cc[2] + b0; v2 = v2 / (1.f + __expf(-v2));
                float v3 = cc[3] + b1; v3 = v3 / (1.f + __expf(-v3));
                *reinterpret_cast<__half2*>(A + rA * SA_H + col) = __floats2half2_rn(v0, v1);
                *reinterpret_cast<__half2*>(A + rB * SA_H + col) = __floats2half2_rn(v2, v3);
            }
        }
    }

    // ---- final projection (reuse c; garbage cols never stored) ----
#pragma unroll
    for (int i = 0; i < 2 * NTWF * 4; i++) c[i] = 0.f;
    gemm16<256, WRF, NTWF>(Wf, NVF, A, Wb, c, tid, lane, wm, wn);

    if (MODE == 0) {
        if (wn == 0 && t == 0) {
#pragma unroll
            for (int mt = 0; mt < 2; mt++) {
                int rA = row0 + 32 * wm + 16 * mt + g, rB = rA + 8;
                out[(size_t)rA * 2 + 0] = c[mt * NTWF * 4 + 0];
                out[(size_t)rA * 2 + 1] = c[mt * NTWF * 4 + 1];
                out[(size_t)rB * 2 + 0] = c[mt * NTWF * 4 + 2];
                out[(size_t)rB * 2 + 1] = c[mt * NTWF * 4 + 3];
            }
        }
    } else {
#pragma unroll
        for (int mt = 0; mt < 2; mt++) {
            int rA = row0 + 32 * wm + 16 * mt + g, rB = rA + 8;
#pragma unroll
            for (int nt = 0; nt < NTWF; nt++) {
                int col = wn * (NTWF * 8) + nt * 8 + 2 * t;
                const float* cc = c + (mt * NTWF + nt) * 4;
                if (rA < nrows) {
                    if (col < 95)     out[(size_t)rA * 95 + col]     = cc[0];
                    if (col + 1 < 95) out[(size_t)rA * 95 + col + 1] = cc[1];
                }
                if (rB < nrows) {
                    if (col < 95)     out[(size_t)rB * 95 + col]     = cc[2];
                    if (col + 1 < 95) out[(size_t)rB * 95 + col + 1] = cc[3];
                }
            }
        }
    }
}

// ---------------- one fused launch: edge blocks then node blocks ----------------
__global__ void __launch_bounds__(256, 2) fused_all(
    const float* __restrict__ m, const float* __restrict__ rbf, const float* __restrict__ Wr_e,
    const float* __restrict__ lng_e, const float* __restrict__ lnb_e, const float* __restrict__ bd_e,
    const float* __restrict__ lng_n, const float* __restrict__ lnb_n, const float* __restrict__ bd_n,
    float* __restrict__ edge_out, float* __restrict__ node_out)
{
    extern __shared__ unsigned char smraw[];
    if (blockIdx.x < EB) {
        mlp_body<0, 8, 1, 2>(blockIdx.x * 64, m, rbf, Wr_e, lng_e, lnb_e, bd_e,
                             g_wh + EOFF, g_wh + EOFF + 32768, g_wh + EOFF + 229376,
                             edge_out, E_TOT, smraw);
    } else {
        mlp_body<1, 96, 3, 95>((blockIdx.x - EB) * 64, nullptr, nullptr, nullptr,
                               lng_n, lnb_n, bd_n,
                               g_wh + NOFF, g_wh + NOFF + 32768, g_wh + NOFF + 229376,
                               node_out, N_TOT, smraw);
    }
}

// ---------------- prep kernels ----------------
__global__ void cvt_branch(const float* __restrict__ up, const float* __restrict__ wd,
                           const float* __restrict__ fin, int fin_n, int base)
{
    int i = blockIdx.x * 256 + threadIdx.x;
    if (i < 32768)                 g_wh[base + i] = __float2half_rn(up[i]);
    else if (i < 229376)           g_wh[base + i] = __float2half_rn(wd[i - 32768]);
    else if (i < 229376 + fin_n)   g_wh[base + i] = __float2half_rn(fin[i - 229376]);
}

__global__ void zero_agg_kernel(int base)
{
    size_t n = (size_t)N_TOT * 64;
    for (size_t i = (size_t)blockIdx.x * blockDim.x + threadIdx.x; i < n;
         i += (size_t)gridDim.x * blockDim.x)
        g_agg[base + i] = 0.f;
}

__global__ void __launch_bounds__(256) scatter_kernel(
    const float* __restrict__ m, const float* __restrict__ rbf,
    const int* __restrict__ src, const float* __restrict__ Wr)
{
    __shared__ float Wrs[128 * 6];
    for (int idx = threadIdx.x; idx < 128 * 6; idx += 256) Wrs[idx] = Wr[idx];
    __syncthreads();
    int sub = threadIdx.x >> 7;
    int k   = threadIdx.x & 127;
    for (long long e = (long long)blockIdx.x * 2 + sub; e < E_TOT;
         e += (long long)gridDim.x * 2) {
        const float* rb = rbf + e * 6;
        float r0 = __ldg(rb+0), r1 = __ldg(rb+1), r2 = __ldg(rb+2);
        float r3 = __ldg(rb+3), r4 = __ldg(rb+4), r5 = __ldg(rb+5);
        const float* wr = Wrs + k * 6;
        float cc = r0*wr[0] + r1*wr[1] + r2*wr[2] + r3*wr[3] + r4*wr[4] + r5*wr[5];
        float v = m[(size_t)e * 128 + k] * cc;
        int s = __ldg(src + e);
        atomicAdd(g_agg + (size_t)s * 128 + k, v);
    }
}

// ---------------- launch ----------------
extern "C" void kernel_launch(void* const* d_in, const int* in_sizes, int n_in,
                              void* d_out, int out_size)
{
    const float* m       = (const float*)d_in[0];
    const float* rbf     = (const float*)d_in[1];
    const int*   src     = (const int*)  d_in[2];
    const float* W_rbf_e = (const float*)d_in[3];
    const float* W_up_e  = (const float*)d_in[4];
    const float* ln_g_e  = (const float*)d_in[5];
    const float* ln_b_e  = (const float*)d_in[6];
    const float* Wd_e    = (const float*)d_in[7];
    const float* bd_e    = (const float*)d_in[8];
    const float* W_fin_e = (const float*)d_in[9];
    const float* W_rbf_n = (const float*)d_in[10];
    const float* W_up_n  = (const float*)d_in[11];
    const float* ln_g_n  = (const float*)d_in[12];
    const float* ln_b_n  = (const float*)d_in[13];
    const float* Wd_n    = (const float*)d_in[14];
    const float* bd_n    = (const float*)d_in[15];
    const float* W_fin_n = (const float*)d_in[16];

    float* edge_out = (float*)d_out;
    float* node_out = (float*)d_out + (size_t)E_TOT * 2;

    cudaFuncSetAttribute((const void*)fused_all,
                         cudaFuncAttributeMaxDynamicSharedMemorySize, SMEM_BYTES);

    // launch order: 0 cvt_e, 1 cvt_n, 2 zeroA, 3 zeroB, 4 scatter, 5 fused (ncu -s 5)
    cvt_branch<<<(229888 + 255) / 256, 256>>>(W_up_e, Wd_e, W_fin_e, 512,   EOFF);
    cvt_branch<<<(253696 + 255) / 256, 256>>>(W_up_n, Wd_n, W_fin_n, 24320, NOFF);
    zero_agg_kernel<<<256, 256>>>(0);
    zero_agg_kernel<<<256, 256>>>(N_TOT * 64);
    scatter_kernel<<<1184, 256>>>(m, rbf, src, W_rbf_n);
    fused_all<<<EB + NB, 256, SMEM_BYTES>>>(
        m, rbf, W_rbf_e, ln_g_e, ln_b_e, bd_e, ln_g_n, ln_b_n, bd_n,
        edge_out, node_out);
}